// round 10
// baseline (speedup 1.0000x reference)
#include <cuda_runtime.h>
#include <math.h>
#include <stdint.h>

// ---------------- problem constants ----------------
constexpr int cD   = 15000;
constexpr int cE   = 300000;
constexpr int QF   = 201;   // DT+DN+1
constexpr int QFP  = 256;   // shifted K=200, padded to 4 chunks of 64
constexpr int KVF  = 301;   // DT+DN+DE+1
constexpr int KVFP = 320;   // shifted K=300, padded to 5 chunks of 64

// ---------------- scratch (device globals) ----------------
__device__ float g_QhD [(size_t)cD * 128];
__device__ float g_acc [(size_t)cD * 128];
__device__ float g_ssum[cD];
__device__ float g_Wt_lq [QFP  * 128];   // shifted: row k = W[:, k+1]
__device__ float g_Wt_lkv[KVFP * 128];   // shifted
__device__ float g_Wt_q  [128 * 128];    // unshifted (row 0 = W[:,0] = 0)
__device__ float g_Wt_k  [128 * 128];
__device__ float g_Wt_v  [128 * 128];

// ---------------- helpers ----------------
__device__ __forceinline__ float warp_reduce_sum(float v) {
    #pragma unroll
    for (int o = 16; o > 0; o >>= 1) v += __shfl_xor_sync(0xffffffffu, v, o);
    return v;
}
__device__ __forceinline__ float to_tf32(float x) {
    uint32_t u;
    asm("cvt.rna.tf32.f32 %0, %1;" : "=r"(u) : "f"(x));
    return __uint_as_float(u);
}
__device__ __forceinline__ void split_tf32(float x, float& hi, float& lo) {
    hi = to_tf32(x);
    lo = to_tf32(x - hi);
}
// precise-enough cos for |x| <= ~2e4: 2-term Cody-Waite + __cosf (err ~1e-6 abs)
__device__ __forceinline__ float fast_cos(float x) {
    float kf = rintf(x * 0.15915494309189535f);
    float r  = fmaf(-kf, 6.2831854820251465f, x);
    r        = fmaf(-kf, -1.7484556e-7f, r);
    return __cosf(r);
}
__device__ __forceinline__ float leaky(float v) { return (v >= 0.f) ? v : 0.2f * v; }
__device__ __forceinline__ void mma_tf32(float* c, float a0, float a1, float a2, float a3,
                                         float b0, float b1) {
    asm volatile(
        "mma.sync.aligned.m16n8k8.row.col.f32.tf32.tf32.f32 "
        "{%0,%1,%2,%3}, {%4,%5,%6,%7}, {%8,%9}, {%0,%1,%2,%3};"
        : "+f"(c[0]), "+f"(c[1]), "+f"(c[2]), "+f"(c[3])
        : "r"(__float_as_uint(a0)), "r"(__float_as_uint(a1)),
          "r"(__float_as_uint(a2)), "r"(__float_as_uint(a3)),
          "r"(__float_as_uint(b0)), "r"(__float_as_uint(b1)));
}

// ---------------- smem layouts ----------------
constexpr int ACT_F   = 128 * 132;          // stride 132
constexpr int BMAT_F  = 64 * 136;           // stride 136

// E: [act | bmat | ss | s | t | w | dst | dtv]; stage aliases act
constexpr int E_BMAT = ACT_F;
constexpr int E_SS   = E_BMAT + BMAT_F;
constexpr int E_S    = E_SS + 128;
constexpr int E_T    = E_S + 128;
constexpr int E_W    = E_T + 128;
constexpr int E_DST  = E_W + 128;
constexpr int E_DTV  = E_DST + 128;
constexpr int E_TOTAL_F = E_DTV + 128;      // ~103.5 KB

// D: [act | q | bmat | ss | s | t | sq | tq | w | ztf]; stage aliases q
constexpr int D_Q    = ACT_F;
constexpr int D_BMAT = D_Q + ACT_F;
constexpr int D_SS   = D_BMAT + BMAT_F;
constexpr int D_S    = D_SS + 128;
constexpr int D_T    = D_S + 128;
constexpr int D_SQ   = D_T + 128;
constexpr int D_TQ   = D_SQ + 128;
constexpr int D_W    = D_TQ + 128;
constexpr int D_ZTF  = D_W + 128;
constexpr int D_TOTAL_F = D_ZTF + 128;      // ~169.5 KB

// one K-chunk (64) of 3xTF32 mma. warp tile = 32 rows x 64 cols.
__device__ __forceinline__ void mma_chunk(float (&c)[2][8][4], const float* sA, int ldA,
                                          const float* sB,
                                          int warpM, int warpN, int g, int tig) {
    #pragma unroll
    for (int kt = 0; kt < 8; kt++) {
        const int k0 = kt * 8;
        float ah[2][4], al[2][4];
        #pragma unroll
        for (int mt = 0; mt < 2; mt++) {
            const float* pr = sA + (warpM * 32 + mt * 16 + g) * ldA + k0 + tig;
            split_tf32(pr[0],            ah[mt][0], al[mt][0]);
            split_tf32(pr[8 * ldA],      ah[mt][1], al[mt][1]);
            split_tf32(pr[4],            ah[mt][2], al[mt][2]);
            split_tf32(pr[8 * ldA + 4],  ah[mt][3], al[mt][3]);
        }
        #pragma unroll
        for (int nt = 0; nt < 8; nt++) {
            int col = warpN * 64 + nt * 8 + g;
            float b0h, b0l, b1h, b1l;
            split_tf32(sB[(k0 + tig) * 136 + col],     b0h, b0l);
            split_tf32(sB[(k0 + tig + 4) * 136 + col], b1h, b1l);
            #pragma unroll
            for (int mt = 0; mt < 2; mt++) {
                mma_tf32(c[mt][nt], al[mt][0], al[mt][1], al[mt][2], al[mt][3], b0h, b1h);
                mma_tf32(c[mt][nt], ah[mt][0], ah[mt][1], ah[mt][2], ah[mt][3], b0l, b1l);
                mma_tf32(c[mt][nt], ah[mt][0], ah[mt][1], ah[mt][2], ah[mt][3], b0h, b1h);
            }
        }
    }
}

__device__ __forceinline__ void zero_c(float (&c)[2][8][4]) {
    #pragma unroll
    for (int mt = 0; mt < 2; mt++)
        #pragma unroll
        for (int nt = 0; nt < 8; nt++)
            #pragma unroll
            for (int i = 0; i < 4; i++) c[mt][nt][i] = 0.f;
}

__device__ __forceinline__ void stage_B(float* sB, const float* Wsrc, int tid) {
    #pragma unroll
    for (int idx = tid; idx < 64 * 32; idx += 256) {
        int k = idx >> 5, n4 = (idx & 31) << 2;
        float4 v = *reinterpret_cast<const float4*>(Wsrc + k * 128 + n4);
        *reinterpret_cast<float4*>(sB + k * 136 + n4) = v;
    }
}

// epilogue: x = scale_row * C + bias; store to buf; accumulate sum_{col>=1} x^2
// into s_ss (pre-zeroed) via 2 shfls + 1 atomic per row-fragment.
__device__ __forceinline__ void epilogue_x(const float (&c)[2][8][4], float* buf,
                                           const float* __restrict__ bias,
                                           const float* s_scale, float* s_ss,
                                           int warpM, int warpN, int g, int tig) {
    #pragma unroll
    for (int mt = 0; mt < 2; mt++) {
        int row = warpM * 32 + mt * 16 + g;
        float sc0 = s_scale[row], sc1 = s_scale[row + 8];
        float sq0 = 0.f, sq1 = 0.f;
        #pragma unroll
        for (int nt = 0; nt < 8; nt++) {
            int col = warpN * 64 + nt * 8 + tig * 2;
            float b0 = bias[col], b1 = bias[col + 1];
            float v00 = fmaf(sc0, c[mt][nt][0], b0);
            float v01 = fmaf(sc0, c[mt][nt][1], b1);
            float v10 = fmaf(sc1, c[mt][nt][2], b0);
            float v11 = fmaf(sc1, c[mt][nt][3], b1);
            buf[row * 132 + col]           = v00;
            buf[row * 132 + col + 1]       = v01;
            buf[(row + 8) * 132 + col]     = v10;
            buf[(row + 8) * 132 + col + 1] = v11;
            sq0 += (col == 0) ? 0.f : v00 * v00;
            sq0 += v01 * v01;
            sq1 += (col == 0) ? 0.f : v10 * v10;
            sq1 += v11 * v11;
        }
        sq0 += __shfl_xor_sync(0xffffffffu, sq0, 1);
        sq0 += __shfl_xor_sync(0xffffffffu, sq0, 2);
        sq1 += __shfl_xor_sync(0xffffffffu, sq1, 1);
        sq1 += __shfl_xor_sync(0xffffffffu, sq1, 2);
        if (tig == 0) {
            atomicAdd(&s_ss[row], sq0);
            atomicAdd(&s_ss[row + 8], sq1);
        }
    }
}

// ---------------- weight prep ----------------
__global__ void prep_weights(const float* __restrict__ lqW, const float* __restrict__ lkvW,
                             const float* __restrict__ wqW, const float* __restrict__ wkW,
                             const float* __restrict__ wvW) {
    int m = blockIdx.y;
    const float* W; float* O; int cols, colsPad; int shift;
    if (m == 0)      { W = lqW;  O = g_Wt_lq;  cols = QF;  colsPad = QFP;  shift = 1; }
    else if (m == 1) { W = lkvW; O = g_Wt_lkv; cols = KVF; colsPad = KVFP; shift = 1; }
    else if (m == 2) { W = wqW;  O = g_Wt_q;   cols = 128; colsPad = 128;  shift = 0; }
    else if (m == 3) { W = wkW;  O = g_Wt_k;   cols = 128; colsPad = 128;  shift = 0; }
    else             { W = wvW;  O = g_Wt_v;   cols = 128; colsPad = 128;  shift = 0; }
    int idx = blockIdx.x * blockDim.x + threadIdx.x;
    if (idx < colsPad * 128) {
        int k = idx >> 7, n = idx & 127;
        int ks = k + shift;
        O[idx] = (ks < cols) ? W[n * cols + ks] : 0.f;
    }
}

// ---------------- D kernel: fused node path ----------------
__global__ __launch_bounds__(256, 1) void d_kernel(
    const float* __restrict__ h, const float* __restrict__ te_b,
    const float* __restrict__ lq_b, const float* __restrict__ lq_s,
    const float* __restrict__ wq_b, const float* __restrict__ wq_s,
    const float* __restrict__ wk_b, const float* __restrict__ wk_s,
    const float* __restrict__ wv_b, const float* __restrict__ wv_s,
    const float* __restrict__ att) {
    extern __shared__ float sm[];
    float* s_act  = sm;
    float* s_q    = sm + D_Q;
    float* s_stage= sm + D_Q;          // aliases q
    float* s_bmat = sm + D_BMAT;
    float* s_ss   = sm + D_SS;
    float* s_s    = sm + D_S;
    float* s_t    = sm + D_T;
    float* s_sq   = sm + D_SQ;
    float* s_tq   = sm + D_TQ;
    float* s_w    = sm + D_W;
    float* s_ztf  = sm + D_ZTF;
    int tid = threadIdx.x, wid = tid >> 5, lane = tid & 31;
    int g = lane >> 2, tig = lane & 3;
    int warpM = wid >> 1, warpN = wid & 1;
    int d0 = blockIdx.x * 128;

    if (tid < 128) s_ztf[tid] = (tid < 100) ? cosf(te_b[tid]) : 0.f;

    int rr = tid >> 1, half = tid & 1;
    bool rvalid = (d0 + rr) < cD;
    float sqacc = 0.f;

    float c[2][8][4];
    // GEMM1: leaky(raw features, j-space) x shifted Wt_lq (K=256 padded)
    zero_c(c);
    for (int kc = 0; kc < 4; kc++) {
        __syncthreads();
        {
            int kkb = half * 32;
            #pragma unroll
            for (int f = 0; f < 8; f++) {
                int kk = kkb + f * 4;
                int j = kc * 64 + kk;
                float4 v = make_float4(0.f, 0.f, 0.f, 0.f);
                if (rvalid) {
                    if (j < 100)
                        v = *reinterpret_cast<const float4*>(h + (size_t)(d0 + rr) * 100 + j);
                    else if (j < 200)
                        v = *reinterpret_cast<const float4*>(s_ztf + (j - 100));
                }
                sqacc = fmaf(v.x, v.x, sqacc); sqacc = fmaf(v.y, v.y, sqacc);
                sqacc = fmaf(v.z, v.z, sqacc); sqacc = fmaf(v.w, v.w, sqacc);
                float4 l = make_float4(leaky(v.x), leaky(v.y), leaky(v.z), leaky(v.w));
                *reinterpret_cast<float4*>(s_stage + rr * 68 + kk) = l;
            }
        }
        stage_B(s_bmat, g_Wt_lq + kc * 64 * 128, tid);
        __syncthreads();
        mma_chunk(c, s_stage, 68, s_bmat, warpM, warpN, g, tig);
    }
    sqacc += __shfl_xor_sync(0xffffffffu, sqacc, 1);
    __syncthreads();
    if (half == 0) s_ss[rr] = sqacc;
    __syncthreads();
    // stats1: expmap scale
    if (tid < 128) {
        float n = sqrtf(fmaxf(s_ss[tid], 1e-8f));
        s_s[tid]  = sinhf(n) / n;
        s_ss[tid] = 0.f;
    }
    __syncthreads();
    epilogue_x(c, s_act, lq_b, s_s, s_ss, warpM, warpN, g, tig);   // act = x1 raw
    __syncthreads();
    // stats2: s1 (t1 unused; col0 has zero weights downstream)
    float esc1 = expf(*lq_s);
    if (tid < 128) {
        float x0 = s_act[tid * 132];
        float t  = esc1 / (1.f + expf(-x0)) + 1.1f;
        s_s[tid]  = sqrtf((t * t - 1.f) / fmaxf(s_ss[tid], 1e-8f));
        s_ss[tid] = 0.f;
    }
    __syncthreads();

    // GEMM wq: x1 -> x_q (scale s1 deferred into epilogue)
    zero_c(c);
    for (int kc = 0; kc < 2; kc++) {
        __syncthreads();
        stage_B(s_bmat, g_Wt_q + kc * 64 * 128, tid);
        __syncthreads();
        mma_chunk(c, s_act + kc * 64, 132, s_bmat, warpM, warpN, g, tig);
    }
    __syncthreads();
    epilogue_x(c, s_q, wq_b, s_s, s_ss, warpM, warpN, g, tig);     // q = x_q raw
    __syncthreads();
    float escq = expf(*wq_s);
    if (tid < 128) {
        float x0 = s_q[tid * 132];
        float t  = escq / (1.f + expf(-x0)) + 1.1f;
        s_tq[tid] = t;
        s_sq[tid] = sqrtf((t * t - 1.f) / fmaxf(s_ss[tid], 1e-8f));
        s_ss[tid] = 0.f;
    }
    __syncthreads();
    // store Qh (transformed) to global
    for (int idx = tid; idx < 128 * 32; idx += 256) {
        int r = idx >> 5, f = (idx & 31) << 2;
        if ((d0 + r) < cD) {
            float4 v = *reinterpret_cast<const float4*>(s_q + r * 132 + f);
            float s = s_sq[r];
            v.x *= s; v.y *= s; v.z *= s; v.w *= s;
            if (f == 0) v.x = s_tq[r];
            *reinterpret_cast<float4*>(g_QhD + (size_t)(d0 + r) * 128 + f) = v;
        }
    }

    // GEMM wk: x1 -> x_k (scale s1 = s_s still valid)
    zero_c(c);
    for (int kc = 0; kc < 2; kc++) {
        __syncthreads();
        stage_B(s_bmat, g_Wt_k + kc * 64 * 128, tid);
        __syncthreads();
        mma_chunk(c, s_act + kc * 64, 132, s_bmat, warpM, warpN, g, tig);
    }
    __syncthreads();
    epilogue_x(c, s_act, wk_b, s_s, s_ss, warpM, warpN, g, tig);   // act = x_k raw
    __syncthreads();
    float esck = expf(*wk_s);
    if (tid < 128) {
        float x0 = s_act[tid * 132];
        float t  = esck / (1.f + expf(-x0)) + 1.1f;
        s_t[tid]  = t;
        s_s[tid]  = sqrtf((t * t - 1.f) / fmaxf(s_ss[tid], 1e-8f));
        s_ss[tid] = 0.f;
    }
    __syncthreads();

    // self logits -> weights
    float attv = *att;
    for (int i = 0; i < 16; i++) {
        int r = wid * 16 + i;
        float sq = s_sq[r], sk = s_s[r];
        float inner = 0.f;
        #pragma unroll
        for (int cc = 0; cc < 4; cc++) {
            int col = lane + cc * 32;
            if (col > 0)
                inner = fmaf(sq * s_q[r * 132 + col], sk * s_act[r * 132 + col], inner);
        }
        inner = warp_reduce_sum(inner);
        if (lane == 0) {
            inner -= s_tq[r] * s_t[r];
            s_w[r] = expf((2.f + 2.f * inner) / attv);
        }
    }
    __syncthreads();

    // GEMM wv: x_k -> x_v (scale s_k = s_s); write into q (x_q dead)
    zero_c(c);
    for (int kc = 0; kc < 2; kc++) {
        __syncthreads();
        stage_B(s_bmat, g_Wt_v + kc * 64 * 128, tid);
        __syncthreads();
        mma_chunk(c, s_act + kc * 64, 132, s_bmat, warpM, warpN, g, tig);
    }
    __syncthreads();
    epilogue_x(c, s_q, wv_b, s_s, s_ss, warpM, warpN, g, tig);     // q = x_v raw
    __syncthreads();
    float escv = expf(*wv_s);
    if (tid < 128) {
        float x0 = s_q[tid * 132];
        float t  = escv / (1.f + expf(-x0)) + 1.1f;
        s_t[tid] = t;
        s_s[tid] = sqrtf((t * t - 1.f) / fmaxf(s_ss[tid], 1e-8f));
    }
    __syncthreads();

    // init acc/ssum with self term
    for (int i = 0; i < 16; i++) {
        int r = wid * 16 + i, d = d0 + r;
        if (d >= cD) continue;
        float wgt = s_w[r], s3 = s_s[r], t3 = s_t[r];
        #pragma unroll
        for (int cc = 0; cc < 4; cc++) {
            int col = lane + cc * 32;
            float v = (col == 0) ? t3 : s_q[r * 132 + col] * s3;
            g_acc[(size_t)d * 128 + col] = wgt * v;
        }
        if (lane == 0) g_ssum[d] = wgt;
    }
}

// ---------------- E kernel: fused edge path ----------------
__global__ __launch_bounds__(256, 2) void e_kernel(
    const float* __restrict__ h, const float* __restrict__ ef,
    const float* __restrict__ dt, const float* __restrict__ te_w,
    const float* __restrict__ te_b,
    const float* __restrict__ lkv_b, const float* __restrict__ lkv_s,
    const float* __restrict__ wk_b, const float* __restrict__ wk_s,
    const float* __restrict__ wv_b, const float* __restrict__ wv_s,
    const float* __restrict__ att, const int* __restrict__ edge_dst) {
    extern __shared__ float sm[];
    float* s_act  = sm;
    float* s_stage= sm;                 // aliases act
    float* s_bmat = sm + E_BMAT;
    float* s_ss   = sm + E_SS;
    float* s_s    = sm + E_S;
    float* s_t    = sm + E_T;
    float* s_w    = sm + E_W;
    int*   s_dst  = reinterpret_cast<int*>(sm + E_DST);
    float* s_dtv  = sm + E_DTV;
    int tid = threadIdx.x, wid = tid >> 5, lane = tid & 31;
    int g = lane >> 2, tig = lane & 3;
    int warpM = wid >> 1, warpN = wid & 1;
    int e0 = blockIdx.x * 128;

    if (tid < 128) {
        int e = e0 + tid;
        bool v = (e < cE);
        s_dst[tid] = v ? edge_dst[e] : -1;
        s_dtv[tid] = v ? dt[e] : 0.f;
    }
    __syncthreads();

    int rr = tid >> 1, half = tid & 1;
    bool rvalid = (e0 + rr) < cE;
    float dte = s_dtv[rr];
    float sqacc = 0.f;

    float c[2][8][4];
    // GEMM1: leaky(raw features, j-space) x shifted Wt_lkv (K=320, 5 chunks)
    zero_c(c);
    for (int kc = 0; kc < 5; kc++) {
        __syncthreads();
        {
            int kkb = half * 32;
            #pragma unroll
            for (int f = 0; f < 8; f++) {
                int kk = kkb + f * 4;
                int j = kc * 64 + kk;
                float4 v = make_float4(0.f, 0.f, 0.f, 0.f);
                if (rvalid) {
                    if (j < 100)
                        v = *reinterpret_cast<const float4*>(h + (size_t)(cD + e0 + rr) * 100 + j);
                    else if (j < 200)
                        v = *reinterpret_cast<const float4*>(ef + (size_t)(e0 + rr) * 100 + (j - 100));
                    else if (j < 300) {
                        int jj = j - 200;
                        float4 w4 = *reinterpret_cast<const float4*>(te_w + jj);
                        float4 b4 = *reinterpret_cast<const float4*>(te_b + jj);
                        v.x = fast_cos(fmaf(dte, w4.x, b4.x));
                        v.y = fast_cos(fmaf(dte, w4.y, b4.y));
                        v.z = fast_cos(fmaf(dte, w4.z, b4.z));
                        v.w = fast_cos(fmaf(dte, w4.w, b4.w));
                    }
                }
                sqacc = fmaf(v.x, v.x, sqacc); sqacc = fmaf(v.y, v.y, sqacc);
                sqacc = fmaf(v.z, v.z, sqacc); sqacc = fmaf(v.w, v.w, sqacc);
                float4 l = make_float4(leaky(v.x), leaky(v.y), leaky(v.z), leaky(v.w));
                *reinterpret_cast<float4*>(s_stage + rr * 68 + kk) = l;
            }
        }
        stage_B(s_bmat, g_Wt_lkv + kc * 64 * 128, tid);
        __syncthreads();
        mma_chunk(c, s_stage, 68, s_bmat, warpM, warpN, g, tig);
    }
    sqacc += __shfl_xor_sync(0xffffffffu, sqacc, 1);
    __syncthreads();
    if (half == 0) s_ss[rr] = sqacc;
    __syncthreads();
    if (tid < 128) {
        float n = sqrtf(fmaxf(s_ss[tid], 1e-8f));
        s_s[tid]  = sinhf(n) / n;
        s_ss[tid] = 0.f;
    }
    __syncthreads();
    epilogue_x(c, s_act, lkv_b, s_s, s_ss, warpM, warpN, g, tig);  // act = x1 raw
    __syncthreads();
    float esc1 = expf(*lkv_s);
    if (tid < 128) {
        float x0 = s_act[tid * 132];
        float t  = esc1 / (1.f + expf(-x0)) + 1.1f;
        s_s[tid]  = sqrtf((t * t - 1.f) / fmaxf(s_ss[tid], 1e-8f));
        s_ss[tid] = 0.f;
    }
    __syncthreads();

    // GEMM wk: x1 -> x_k
    zero_c(c);
    for (int kc = 0; kc < 2; kc++) {
        __syncthreads();
        stage_B(s_bmat, g_Wt_k + kc * 64 * 128, tid);
        __syncthreads();
        mma_chunk(c, s_act + kc * 64, 132, s_bmat, warpM, warpN, g, tig);
    }
    __syncthreads();
    epilogue_x(c, s_act, wk_b, s_s, s_ss, warpM, warpN, g, tig);   // act = x_k raw
    __syncthreads();
    float esck = expf(*wk_s);
    if (tid < 128) {
        float x0 = s_act[tid * 132];
        float t  = esck / (1.f + expf(-x0)) + 1.1f;
        s_t[tid]  = t;
        s_s[tid]  = sqrtf((t * t - 1.f) / fmaxf(s_ss[tid], 1e-8f));
        s_ss[tid] = 0.f;
    }
    __syncthreads();

    // logits + ssum atomics (Kh applied on the fly from raw x_k)
    float attv = *att;
    for (int i = 0; i < 16; i++) {
        int r = wid * 16 + i;
        int dv = s_dst[r];
        float inner = 0.f;
        float sk = s_s[r];
        if (dv >= 0) {
            #pragma unroll
            for (int cc = 0; cc < 4; cc++) {
                int col = lane + cc * 32;
                if (col > 0)
                    inner = fmaf(sk * s_act[r * 132 + col],
                                 g_QhD[(size_t)dv * 128 + col], inner);
            }
        }
        inner = warp_reduce_sum(inner);
        if (lane == 0 && dv >= 0) {
            inner -= s_t[r] * g_QhD[(size_t)dv * 128];
            float wgt = expf((2.f + 2.f * inner) / attv);
            s_w[r] = wgt;
            atomicAdd(&g_ssum[dv], wgt);
        }
    }
    __syncthreads();

    // GEMM wv: x_k -> x_v (scale s_k = s_s)
    zero_c(c);
    for (int kc = 0; kc < 2; kc++) {
        __syncthreads();
        stage_B(s_bmat, g_Wt_v + kc * 64 * 128, tid);
        __syncthreads();
        mma_chunk(c, s_act + kc * 64, 132, s_bmat, warpM, warpN, g, tig);
    }
    __syncthreads();
    epilogue_x(c, s_act, wv_b, s_s, s_ss, warpM, warpN, g, tig);   // act = x_v raw
    __syncthreads();
    float escv = expf(*wv_s);
    if (tid < 128) {
        float x0 = s_act[tid * 132];
        float t  = escv / (1.f + expf(-x0)) + 1.1f;
        s_t[tid] = t;
        s_s[tid] = sqrtf((t * t - 1.f) / fmaxf(s_ss[tid], 1e-8f));
    }
    __syncthreads();

    // weighted scatter
    for (int i = 0; i < 16; i++) {
        int r = wid * 16 + i;
        int dv = s_dst[r];
        if (dv < 0) continue;
        float wgt = s_w[r], s3 = s_s[r], t3 = s_t[r];
        #pragma unroll
        for (int cc = 0; cc < 4; cc++) {
            int col = lane + cc * 32;
            float v = (col == 0) ? t3 : s_act[r * 132 + col] * s3;
            atomicAdd(&g_acc[(size_t)dv * 128 + col], wgt * v);
        }
    }
}

// ---------------- finalize ----------------
__global__ void finalize_kernel(float* __restrict__ out) {
    int d = blockIdx.x * 4 + (threadIdx.x >> 5);
    int lane = threadIdx.x & 31;
    if (d >= cD) return;
    float inv_s = 1.f / g_ssum[d];
    float rv[4];
    float sq = 0.f;
    #pragma unroll
    for (int i = 0; i < 4; i++) {
        int c = lane + 32 * i;
        float v = g_acc[(size_t)d * 128 + c] * inv_s;
        rv[i] = v;
        if (c != 0) sq += v * v;
    }
    sq = warp_reduce_sum(sq);
    float r0 = __shfl_sync(0xffffffffu, rv[0], 0);
    float neg_inner = r0 * r0 - sq;
    float denom = sqrtf(fmaxf(fabsf(neg_inner), 1e-8f));
    float a = fmaxf(r0 / denom, 1.f + 1e-7f);
    float coef = acoshf(a) / sqrtf(fmaxf(a * a - 1.f, 1e-8f));
    #pragma unroll
    for (int i = 0; i < 4; i++) {
        int c = lane + 32 * i;
        out[(size_t)d * 128 + c] = (c == 0) ? 0.f : coef * (rv[i] / denom);
    }
}

// ---------------- launch ----------------
extern "C" void kernel_launch(void* const* d_in, const int* in_sizes, int n_in,
                              void* d_out, int out_size) {
    const float* h     = (const float*)d_in[0];
    const float* ef    = (const float*)d_in[1];
    const float* dt    = (const float*)d_in[2];
    const float* te_w  = (const float*)d_in[3];
    const float* te_b  = (const float*)d_in[4];
    const float* lq_W  = (const float*)d_in[5];
    const float* lq_b  = (const float*)d_in[6];
    const float* lq_s  = (const float*)d_in[7];
    const float* lkv_W = (const float*)d_in[8];
    const float* lkv_b = (const float*)d_in[9];
    const float* lkv_s = (const float*)d_in[10];
    const float* wq_W  = (const float*)d_in[11];
    const float* wq_b  = (const float*)d_in[12];
    const float* wq_s  = (const float*)d_in[13];
    const float* wk_W  = (const float*)d_in[14];
    const float* wk_b  = (const float*)d_in[15];
    const float* wk_s  = (const float*)d_in[16];
    const float* wv_W  = (const float*)d_in[17];
    const float* wv_b  = (const float*)d_in[18];
    const float* wv_s  = (const float*)d_in[19];
    const float* att   = (const float*)d_in[20];
    const int*   edst  = (const int*)d_in[21];
    float* out = (float*)d_out;

    cudaFuncSetAttribute(d_kernel, cudaFuncAttributeMaxDynamicSharedMemorySize,
                         D_TOTAL_F * 4);
    cudaFuncSetAttribute(e_kernel, cudaFuncAttributeMaxDynamicSharedMemorySize,
                         E_TOTAL_F * 4);

    prep_weights<<<dim3((KVFP * 128 + 255) / 256, 5), 256>>>(lq_W, lkv_W, wq_W, wk_W, wv_W);
    d_kernel<<<(cD + 127) / 128, 256, D_TOTAL_F * 4>>>(
        h, te_b, lq_b, lq_s, wq_b, wq_s, wk_b, wk_s, wv_b, wv_s, att);
    e_kernel<<<(cE + 127) / 128, 256, E_TOTAL_F * 4>>>(
        h, ef, dt, te_w, te_b, lkv_b, lkv_s, wk_b, wk_s, wv_b, wv_s, att, edst);
    finalize_kernel<<<(cD + 3) / 4, 128>>>(out);
}

// round 14
// speedup vs baseline: 1.5754x; 1.5754x over previous
#include <cuda_runtime.h>
#include <math.h>
#include <stdint.h>

// ---------------- problem constants ----------------
constexpr int cD   = 15000;
constexpr int cE   = 300000;
constexpr int QF   = 201;   // DT+DN+1
constexpr int QFP  = 256;   // shifted K=200, padded (4 chunks of 64)
constexpr int KVF  = 301;   // DT+DN+DE+1
constexpr int KVFP = 320;   // shifted K=300, padded (5 chunks of 64)

// ---------------- global scratch ----------------
__device__ float g_QhD [(size_t)cD * 128];
__device__ float g_acc [(size_t)cD * 128];
__device__ float g_ssum[cD];
// pre-split bf16 weights, N-major [n][k] (k contiguous), shifted by 1 input col
__device__ __align__(16) uint16_t g_Wh_lq [128 * QFP];
__device__ __align__(16) uint16_t g_Wl_lq [128 * QFP];
__device__ __align__(16) uint16_t g_Wh_lkv[128 * KVFP];
__device__ __align__(16) uint16_t g_Wl_lkv[128 * KVFP];
__device__ __align__(16) uint16_t g_Wh_q[128 * 128], g_Wl_q[128 * 128];
__device__ __align__(16) uint16_t g_Wh_k[128 * 128], g_Wl_k[128 * 128];
__device__ __align__(16) uint16_t g_Wh_v[128 * 128], g_Wl_v[128 * 128];

// ---------------- helpers ----------------
__device__ __forceinline__ float warp_reduce_sum(float v) {
    #pragma unroll
    for (int o = 16; o > 0; o >>= 1) v += __shfl_xor_sync(0xffffffffu, v, o);
    return v;
}
// precise-enough cos for |x| <= ~2e4 (err ~1e-6 abs)
__device__ __forceinline__ float fast_cos(float x) {
    float kf = rintf(x * 0.15915494309189535f);
    float r  = fmaf(-kf, 6.2831854820251465f, x);
    r        = fmaf(-kf, -1.7484556e-7f, r);
    return __cosf(r);
}
__device__ __forceinline__ float leaky(float v) { return (v >= 0.f) ? v : 0.2f * v; }
// pack2(v0,v1): low half = bf16(v0), high half = bf16(v1)
__device__ __forceinline__ uint32_t pack2(float v0, float v1) {
    uint32_t r;
    asm("cvt.rn.bf16x2.f32 %0, %1, %2;" : "=r"(r) : "f"(v1), "f"(v0));
    return r;
}
__device__ __forceinline__ float bf_lo_f(uint32_t p) { return __uint_as_float(p << 16); }
__device__ __forceinline__ float bf_hi_f(uint32_t p) { return __uint_as_float(p & 0xffff0000u); }
__device__ __forceinline__ uint32_t lds32(const uint16_t* p) {
    return *reinterpret_cast<const uint32_t*>(p);
}
// recombine split bf16 element
__device__ __forceinline__ float rc(const uint16_t* H, const uint16_t* L, int idx) {
    uint32_t h = H[idx], l = L[idx];
    return __uint_as_float(h << 16) + __uint_as_float(l << 16);
}
__device__ __forceinline__ void mma_bf16(float* c, uint32_t a0, uint32_t a1,
                                         uint32_t a2, uint32_t a3,
                                         uint32_t b0, uint32_t b1) {
    asm volatile(
        "mma.sync.aligned.m16n8k16.row.col.f32.bf16.bf16.f32 "
        "{%0,%1,%2,%3}, {%4,%5,%6,%7}, {%8,%9}, {%0,%1,%2,%3};"
        : "+f"(c[0]), "+f"(c[1]), "+f"(c[2]), "+f"(c[3])
        : "r"(a0), "r"(a1), "r"(a2), "r"(a3), "r"(b0), "r"(b1));
}

// ---------------- smem layouts (u16 units) ----------------
constexpr int LDA = 136;   // act k-stride (272B; conflict-free for frag loads)
constexpr int LDB = 72;    // bmat k-stride (144B)

// E: [actH | actL | bmH | bmL | f32: ss s t w dst dtv]
constexpr int E_U_ACTH = 0;
constexpr int E_U_ACTL = 128 * LDA;
constexpr int E_U_BMH  = 2 * 128 * LDA;
constexpr int E_U_BML  = E_U_BMH + 128 * LDB;
constexpr int E_F_BASE = (E_U_BML + 128 * LDB) / 2;
constexpr int E_F_SS  = E_F_BASE,      E_F_S   = E_F_SS + 128;
constexpr int E_F_T   = E_F_S + 128,   E_F_W   = E_F_T + 128;
constexpr int E_F_DST = E_F_W + 128,   E_F_DTV = E_F_DST + 128;
constexpr int E_TOTAL_B = (E_F_DTV + 128) * 4;          // 109,568 B

// D: [actH | actL | qH | qL | bmH | bmL | f32: ss s t sq tq w ztf]
constexpr int D_U_ACTH = 0;
constexpr int D_U_ACTL = 128 * LDA;
constexpr int D_U_QH   = 2 * 128 * LDA;
constexpr int D_U_QL   = D_U_QH + 128 * LDA;
constexpr int D_U_BMH  = D_U_QL + 128 * LDA;
constexpr int D_U_BML  = D_U_BMH + 128 * LDB;
constexpr int D_F_BASE = (D_U_BML + 128 * LDB) / 2;
constexpr int D_F_SS  = D_F_BASE,      D_F_S   = D_F_SS + 128;
constexpr int D_F_T   = D_F_S + 128,   D_F_SQ  = D_F_T + 128;
constexpr int D_F_TQ  = D_F_SQ + 128,  D_F_W   = D_F_TQ + 128;
constexpr int D_F_ZTF = D_F_W + 128;
constexpr int D_TOTAL_B = (D_F_ZTF + 128) * 4;          // 179,712 B

// one 64-K chunk of 3-term bf16x2 mma (pre-split operands in smem)
__device__ __forceinline__ void mma_chunk(float (&c)[2][8][4],
        const uint16_t* Ah, const uint16_t* Al,
        const uint16_t* Bh, const uint16_t* Bl,
        int warpM, int warpN, int lane) {
    int qr = lane >> 2, qc = (lane & 3) * 2;
    #pragma unroll
    for (int kt = 0; kt < 4; kt++) {
        int k0 = kt * 16;
        uint32_t ah[2][4], al[2][4];
        #pragma unroll
        for (int mt = 0; mt < 2; mt++) {
            const uint16_t* ph = Ah + (warpM * 32 + mt * 16 + qr) * LDA + k0 + qc;
            const uint16_t* pl = Al + (warpM * 32 + mt * 16 + qr) * LDA + k0 + qc;
            ah[mt][0] = lds32(ph);               al[mt][0] = lds32(pl);
            ah[mt][1] = lds32(ph + 8 * LDA);     al[mt][1] = lds32(pl + 8 * LDA);
            ah[mt][2] = lds32(ph + 8);           al[mt][2] = lds32(pl + 8);
            ah[mt][3] = lds32(ph + 8 * LDA + 8); al[mt][3] = lds32(pl + 8 * LDA + 8);
        }
        #pragma unroll
        for (int nt = 0; nt < 8; nt++) {
            int n = warpN * 64 + nt * 8 + qr;
            const uint16_t* pbh = Bh + n * LDB + k0 + qc;
            const uint16_t* pbl = Bl + n * LDB + k0 + qc;
            uint32_t bh0 = lds32(pbh), bh1 = lds32(pbh + 8);
            uint32_t bl0 = lds32(pbl), bl1 = lds32(pbl + 8);
            #pragma unroll
            for (int mt = 0; mt < 2; mt++) {
                mma_bf16(c[mt][nt], al[mt][0], al[mt][1], al[mt][2], al[mt][3], bh0, bh1);
                mma_bf16(c[mt][nt], ah[mt][0], ah[mt][1], ah[mt][2], ah[mt][3], bl0, bl1);
                mma_bf16(c[mt][nt], ah[mt][0], ah[mt][1], ah[mt][2], ah[mt][3], bh0, bh1);
            }
        }
    }
}

__device__ __forceinline__ void zero_c(float (&c)[2][8][4]) {
    #pragma unroll
    for (int mt = 0; mt < 2; mt++)
        #pragma unroll
        for (int nt = 0; nt < 8; nt++)
            #pragma unroll
            for (int i = 0; i < 4; i++) c[mt][nt][i] = 0.f;
}

// stage one 64-k chunk of pre-split weights (global -> smem), int4 copies
__device__ __forceinline__ void stage_W(uint16_t* Bh, uint16_t* Bl,
        const uint16_t* Gh, const uint16_t* Gl, int KP, int kc, int tid) {
    #pragma unroll
    for (int idx = tid; idx < 128 * 8; idx += 256) {
        int row = idx >> 3, o = idx & 7;
        const int4* sh = reinterpret_cast<const int4*>(Gh + row * KP + kc * 64) + o;
        const int4* sl = reinterpret_cast<const int4*>(Gl + row * KP + kc * 64) + o;
        *(reinterpret_cast<int4*>(Bh + row * LDB) + o) = *sh;
        *(reinterpret_cast<int4*>(Bl + row * LDB) + o) = *sl;
    }
}

// epilogue: v = scale_row*C + bias; split-store bf16 hi/lo; accumulate sum_{col>=1} v^2
__device__ __forceinline__ void epi_bf(const float (&c)[2][8][4],
        uint16_t* Ah, uint16_t* Al,
        const float* __restrict__ bias, const float* s_scale, float* s_ss,
        int warpM, int warpN, int g, int tig) {
    #pragma unroll
    for (int mt = 0; mt < 2; mt++) {
        int row = warpM * 32 + mt * 16 + g;
        float sc0 = s_scale[row], sc1 = s_scale[row + 8];
        float sq0 = 0.f, sq1 = 0.f;
        #pragma unroll
        for (int nt = 0; nt < 8; nt++) {
            int col = warpN * 64 + nt * 8 + tig * 2;
            float b0 = bias[col], b1 = bias[col + 1];
            float v00 = fmaf(sc0, c[mt][nt][0], b0);
            float v01 = fmaf(sc0, c[mt][nt][1], b1);
            float v10 = fmaf(sc1, c[mt][nt][2], b0);
            float v11 = fmaf(sc1, c[mt][nt][3], b1);
            sq0 += ((col == 0) ? 0.f : v00 * v00) + v01 * v01;
            sq1 += ((col == 0) ? 0.f : v10 * v10) + v11 * v11;
            uint32_t h0 = pack2(v00, v01);
            uint32_t l0 = pack2(v00 - bf_lo_f(h0), v01 - bf_hi_f(h0));
            *reinterpret_cast<uint32_t*>(Ah + row * LDA + col) = h0;
            *reinterpret_cast<uint32_t*>(Al + row * LDA + col) = l0;
            uint32_t h1 = pack2(v10, v11);
            uint32_t l1 = pack2(v10 - bf_lo_f(h1), v11 - bf_hi_f(h1));
            *reinterpret_cast<uint32_t*>(Ah + (row + 8) * LDA + col) = h1;
            *reinterpret_cast<uint32_t*>(Al + (row + 8) * LDA + col) = l1;
        }
        sq0 += __shfl_xor_sync(0xffffffffu, sq0, 1);
        sq0 += __shfl_xor_sync(0xffffffffu, sq0, 2);
        sq1 += __shfl_xor_sync(0xffffffffu, sq1, 1);
        sq1 += __shfl_xor_sync(0xffffffffu, sq1, 2);
        if (tig == 0) {
            atomicAdd(&s_ss[row], sq0);
            atomicAdd(&s_ss[row + 8], sq1);
        }
    }
}

// split a float4 of (already leaky'd) values into bf16 hi/lo pair words
__device__ __forceinline__ void split_store4(uint16_t* H, uint16_t* L, int off,
                                             float l0, float l1, float l2, float l3) {
    uint32_t hA = pack2(l0, l1);
    uint32_t lA = pack2(l0 - bf_lo_f(hA), l1 - bf_hi_f(hA));
    uint32_t hB = pack2(l2, l3);
    uint32_t lB = pack2(l2 - bf_lo_f(hB), l3 - bf_hi_f(hB));
    *reinterpret_cast<uint32_t*>(H + off)     = hA;
    *reinterpret_cast<uint32_t*>(L + off)     = lA;
    *reinterpret_cast<uint32_t*>(H + off + 2) = hB;
    *reinterpret_cast<uint32_t*>(L + off + 2) = lB;
}

// ---------------- weight prep: transpose-free split to bf16, shifted ----------------
__global__ void prep_weights(const float* __restrict__ lqW, const float* __restrict__ lkvW,
                             const float* __restrict__ wqW, const float* __restrict__ wkW,
                             const float* __restrict__ wvW) {
    int m = blockIdx.y;
    const float* W; uint16_t *OH, *OL; int cols, KP, shift;
    if (m == 0)      { W = lqW;  OH = g_Wh_lq;  OL = g_Wl_lq;  cols = QF;  KP = QFP;  shift = 1; }
    else if (m == 1) { W = lkvW; OH = g_Wh_lkv; OL = g_Wl_lkv; cols = KVF; KP = KVFP; shift = 1; }
    else if (m == 2) { W = wqW;  OH = g_Wh_q;   OL = g_Wl_q;   cols = 128; KP = 128;  shift = 0; }
    else if (m == 3) { W = wkW;  OH = g_Wh_k;   OL = g_Wl_k;   cols = 128; KP = 128;  shift = 0; }
    else             { W = wvW;  OH = g_Wh_v;   OL = g_Wl_v;   cols = 128; KP = 128;  shift = 0; }
    int idx = blockIdx.x * blockDim.x + threadIdx.x;
    if (idx < 128 * KP) {
        int n = idx / KP, k = idx % KP;
        float w = (k + shift < cols) ? W[n * cols + k + shift] : 0.f;
        uint32_t ph = pack2(w, 0.f);
        float hf = bf_lo_f(ph);
        uint32_t pl = pack2(w - hf, 0.f);
        OH[idx] = (uint16_t)(ph & 0xffffu);
        OL[idx] = (uint16_t)(pl & 0xffffu);
    }
}

// ---------------- D kernel ----------------
__global__ __launch_bounds__(256, 1) void d_kernel(
    const float* __restrict__ h, const float* __restrict__ te_b,
    const float* __restrict__ lq_b, const float* __restrict__ lq_s,
    const float* __restrict__ wq_b, const float* __restrict__ wq_s,
    const float* __restrict__ wk_b, const float* __restrict__ wk_s,
    const float* __restrict__ wv_b, const float* __restrict__ wv_s,
    const float* __restrict__ att) {
    extern __shared__ __align__(16) char smraw[];
    uint16_t* su = reinterpret_cast<uint16_t*>(smraw);
    float*    sf = reinterpret_cast<float*>(smraw);
    uint16_t *ACTH = su + D_U_ACTH, *ACTL = su + D_U_ACTL;
    uint16_t *QH   = su + D_U_QH,   *QL   = su + D_U_QL;
    uint16_t *BMH  = su + D_U_BMH,  *BML  = su + D_U_BML;
    float *s_ss = sf + D_F_SS, *s_s = sf + D_F_S, *s_t = sf + D_F_T;
    float *s_sq = sf + D_F_SQ, *s_tq = sf + D_F_TQ, *s_w = sf + D_F_W;
    float *s_ztf = sf + D_F_ZTF;
    int tid = threadIdx.x, wid = tid >> 5, lane = tid & 31;
    int g = lane >> 2, tig = lane & 3;
    int warpM = wid >> 1, warpN = wid & 1;
    int d0 = blockIdx.x * 128;

    if (tid < 128) s_ztf[tid] = (tid < 100) ? cosf(te_b[tid]) : 0.f;

    int rr = tid >> 1, half = tid & 1;
    bool rvalid = (d0 + rr) < cD;
    float sqacc = 0.f;

    float c[2][8][4];
    // GEMM1: leaky(raw feats) x Wlq (staged into Q arrays; 4 chunks of 64)
    zero_c(c);
    for (int kc = 0; kc < 4; kc++) {
        __syncthreads();
        int kkb = half * 32;
        #pragma unroll
        for (int f = 0; f < 8; f++) {
            int kk = kkb + f * 4, j = kc * 64 + kk;
            float4 v = make_float4(0.f, 0.f, 0.f, 0.f);
            if (rvalid) {
                if (j < 100)
                    v = *reinterpret_cast<const float4*>(h + (size_t)(d0 + rr) * 100 + j);
                else if (j < 200)
                    v = *reinterpret_cast<const float4*>(s_ztf + (j - 100));
            }
            sqacc = fmaf(v.x, v.x, sqacc); sqacc = fmaf(v.y, v.y, sqacc);
            sqacc = fmaf(v.z, v.z, sqacc); sqacc = fmaf(v.w, v.w, sqacc);
            split_store4(QH, QL, rr * LDA + kk,
                         leaky(v.x), leaky(v.y), leaky(v.z), leaky(v.w));
        }
        stage_W(BMH, BML, g_Wh_lq, g_Wl_lq, QFP, kc, tid);
        __syncthreads();
        mma_chunk(c, QH, QL, BMH, BML, warpM, warpN, lane);
    }
    sqacc += __shfl_xor_sync(0xffffffffu, sqacc, 1);
    __syncthreads();
    if (half == 0) s_ss[rr] = sqacc;
    __syncthreads();
    if (tid < 128) {
        float n = sqrtf(fmaxf(s_ss[tid], 1e-8f));
        s_s[tid]  = sinhf(n) / n;
        s_ss[tid] = 0.f;
    }
    __syncthreads();
    epi_bf(c, ACTH, ACTL, lq_b, s_s, s_ss, warpM, warpN, g, tig);  // act = x1
    __syncthreads();
    float esc1 = expf(*lq_s);
    if (tid < 128) {
        float x0 = rc(ACTH, ACTL, tid * LDA);
        float t  = esc1 / (1.f + expf(-x0)) + 1.1f;
        s_s[tid]  = sqrtf((t * t - 1.f) / fmaxf(s_ss[tid], 1e-8f));
        s_ss[tid] = 0.f;
    }
    __syncthreads();

    // GEMM wq: x1 -> x_q (into Q arrays)
    zero_c(c);
    for (int kc = 0; kc < 2; kc++) {
        __syncthreads();
        stage_W(BMH, BML, g_Wh_q, g_Wl_q, 128, kc, tid);
        __syncthreads();
        mma_chunk(c, ACTH + kc * 64, ACTL + kc * 64, BMH, BML, warpM, warpN, lane);
    }
    __syncthreads();
    epi_bf(c, QH, QL, wq_b, s_s, s_ss, warpM, warpN, g, tig);      // q = x_q
    __syncthreads();
    float escq = expf(*wq_s);
    if (tid < 128) {
        float x0 = rc(QH, QL, tid * LDA);
        float t  = escq / (1.f + expf(-x0)) + 1.1f;
        s_tq[tid] = t;
        s_sq[tid] = sqrtf((t * t - 1.f) / fmaxf(s_ss[tid], 1e-8f));
        s_ss[tid] = 0.f;
    }
    __syncthreads();
    // store Qh to global (recombined, transformed)
    for (int idx = tid; idx < 128 * 64; idx += 256) {
        int r = idx >> 6, p = idx & 63;
        if ((d0 + r) < cD) {
            float s = s_sq[r];
            float v0 = rc(QH, QL, r * LDA + 2 * p) * s;
            float v1 = rc(QH, QL, r * LDA + 2 * p + 1) * s;
            if (p == 0) v0 = s_tq[r];
            *reinterpret_cast<float2*>(g_QhD + (size_t)(d0 + r) * 128 + 2 * p) =
                make_float2(v0, v1);
        }
    }

    // GEMM wk: x1 -> x_k (overwrite act after reads)
    zero_c(c);
    for (int kc = 0; kc < 2; kc++) {
        __syncthreads();
        stage_W(BMH, BML, g_Wh_k, g_Wl_k, 128, kc, tid);
        __syncthreads();
        mma_chunk(c, ACTH + kc * 64, ACTL + kc * 64, BMH, BML, warpM, warpN, lane);
    }
    __syncthreads();
    epi_bf(c, ACTH, ACTL, wk_b, s_s, s_ss, warpM, warpN, g, tig);  // act = x_k
    __syncthreads();
    float esck = expf(*wk_s);
    if (tid < 128) {
        float x0 = rc(ACTH, ACTL, tid * LDA);
        float t  = esck / (1.f + expf(-x0)) + 1.1f;
        s_t[tid]  = t;
        s_s[tid]  = sqrtf((t * t - 1.f) / fmaxf(s_ss[tid], 1e-8f));
        s_ss[tid] = 0.f;
    }
    __syncthreads();

    // self logits -> weights
    float attv = *att;
    for (int i = 0; i < 16; i++) {
        int r = wid * 16 + i;
        float sq = s_sq[r], sk = s_s[r];
        float inner = 0.f;
        #pragma unroll
        for (int cc = 0; cc < 4; cc++) {
            int col = lane + cc * 32;
            if (col > 0)
                inner = fmaf(sq * rc(QH, QL, r * LDA + col),
                             sk * rc(ACTH, ACTL, r * LDA + col), inner);
        }
        inner = warp_reduce_sum(inner);
        if (lane == 0) {
            inner -= s_tq[r] * s_t[r];
            s_w[r] = expf((2.f + 2.f * inner) / attv);
        }
    }
    __syncthreads();

    // GEMM wv: x_k -> x_v (into Q arrays; x_q dead)
    zero_c(c);
    for (int kc = 0; kc < 2; kc++) {
        __syncthreads();
        stage_W(BMH, BML, g_Wh_v, g_Wl_v, 128, kc, tid);
        __syncthreads();
        mma_chunk(c, ACTH + kc * 64, ACTL + kc * 64, BMH, BML, warpM, warpN, lane);
    }
    __syncthreads();
    epi_bf(c, QH, QL, wv_b, s_s, s_ss, warpM, warpN, g, tig);      // q = x_v
    __syncthreads();
    float escv = expf(*wv_s);
    if (tid < 128) {
        float x0 = rc(QH, QL, tid * LDA);
        float t  = escv / (1.f + expf(-x0)) + 1.1f;
        s_t[tid] = t;
        s_s[tid] = sqrtf((t * t - 1.f) / fmaxf(s_ss[tid], 1e-8f));
    }
    __syncthreads();

    // init acc/ssum with self term
    for (int i = 0; i < 16; i++) {
        int r = wid * 16 + i, d = d0 + r;
        if (d >= cD) continue;
        float wgt = s_w[r], s3 = s_s[r], t3 = s_t[r];
        #pragma unroll
        for (int cc = 0; cc < 4; cc++) {
            int col = lane + cc * 32;
            float v = (col == 0) ? t3 : rc(QH, QL, r * LDA + col) * s3;
            g_acc[(size_t)d * 128 + col] = wgt * v;
        }
        if (lane == 0) g_ssum[d] = wgt;
    }
}

// ---------------- E kernel ----------------
__global__ __launch_bounds__(256, 2) void e_kernel(
    const float* __restrict__ h, const float* __restrict__ ef,
    const float* __restrict__ dt, const float* __restrict__ te_w,
    const float* __restrict__ te_b,
    const float* __restrict__ lkv_b, const float* __restrict__ lkv_s,
    const float* __restrict__ wk_b, const float* __restrict__ wk_s,
    const float* __restrict__ wv_b, const float* __restrict__ wv_s,
    const float* __restrict__ att, const int* __restrict__ edge_dst) {
    extern __shared__ __align__(16) char smraw[];
    uint16_t* su = reinterpret_cast<uint16_t*>(smraw);
    float*    sf = reinterpret_cast<float*>(smraw);
    uint16_t *ACTH = su + E_U_ACTH, *ACTL = su + E_U_ACTL;
    uint16_t *BMH  = su + E_U_BMH,  *BML  = su + E_U_BML;
    float *s_ss = sf + E_F_SS, *s_s = sf + E_F_S, *s_t = sf + E_F_T, *s_w = sf + E_F_W;
    int*   s_dst = reinterpret_cast<int*>(sf + E_F_DST);
    float* s_dtv = sf + E_F_DTV;
    int tid = threadIdx.x, wid = tid >> 5, lane = tid & 31;
    int g = lane >> 2, tig = lane & 3;
    int warpM = wid >> 1, warpN = wid & 1;
    int e0 = blockIdx.x * 128;

    if (tid < 128) {
        int e = e0 + tid;
        bool v = (e < cE);
        s_dst[tid] = v ? edge_dst[e] : -1;
        s_dtv[tid] = v ? dt[e] : 0.f;
    }
    __syncthreads();

    int rr = tid >> 1, half = tid & 1;
    bool rvalid = (e0 + rr) < cE;
    float dte = s_dtv[rr];
    float sqacc = 0.f;

    float c[2][8][4];
    // GEMM1: leaky(raw feats) x Wlkv (staged into ACT k[0,64); 5 chunks)
    zero_c(c);
    for (int kc = 0; kc < 5; kc++) {
        __syncthreads();
        int kkb = half * 32;
        #pragma unroll
        for (int f = 0; f < 8; f++) {
            int kk = kkb + f * 4, j = kc * 64 + kk;
            float4 v = make_float4(0.f, 0.f, 0.f, 0.f);
            if (rvalid) {
                if (j < 100)
                    v = *reinterpret_cast<const float4*>(h + (size_t)(cD + e0 + rr) * 100 + j);
                else if (j < 200)
                    v = *reinterpret_cast<const float4*>(ef + (size_t)(e0 + rr) * 100 + (j - 100));
                else if (j < 300) {
                    int jj = j - 200;
                    float4 w4 = *reinterpret_cast<const float4*>(te_w + jj);
                    float4 b4 = *reinterpret_cast<const float4*>(te_b + jj);
                    v.x = fast_cos(fmaf(dte, w4.x, b4.x));
                    v.y = fast_cos(fmaf(dte, w4.y, b4.y));
                    v.z = fast_cos(fmaf(dte, w4.z, b4.z));
                    v.w = fast_cos(fmaf(dte, w4.w, b4.w));
                }
            }
            sqacc = fmaf(v.x, v.x, sqacc); sqacc = fmaf(v.y, v.y, sqacc);
            sqacc = fmaf(v.z, v.z, sqacc); sqacc = fmaf(v.w, v.w, sqacc);
            split_store4(ACTH, ACTL, rr * LDA + kk,
                         leaky(v.x), leaky(v.y), leaky(v.z), leaky(v.w));
        }
        stage_W(BMH, BML, g_Wh_lkv, g_Wl_lkv, KVFP, kc, tid);
        __syncthreads();
        mma_chunk(c, ACTH, ACTL, BMH, BML, warpM, warpN, lane);
    }
    sqacc += __shfl_xor_sync(0xffffffffu, sqacc, 1);
    __syncthreads();
    if (half == 0) s_ss[rr] = sqacc;
    __syncthreads();
    if (tid < 128) {
        float n = sqrtf(fmaxf(s_ss[tid], 1e-8f));
        s_s[tid]  = sinhf(n) / n;
        s_ss[tid] = 0.f;
    }
    __syncthreads();
    epi_bf(c, ACTH, ACTL, lkv_b, s_s, s_ss, warpM, warpN, g, tig); // act = x1
    __syncthreads();
    float esc1 = expf(*lkv_s);
    if (tid < 128) {
        float x0 = rc(ACTH, ACTL, tid * LDA);
        float t  = esc1 / (1.f + expf(-x0)) + 1.1f;
        s_s[tid]  = sqrtf((t * t - 1.f) / fmaxf(s_ss[tid], 1e-8f));
        s_ss[tid] = 0.f;
    }
    __syncthreads();

    // GEMM wk: x1 -> x_k
    zero_c(c);
    for (int kc = 0; kc < 2; kc++) {
        __syncthreads();
        stage_W(BMH, BML, g_Wh_k, g_Wl_k, 128, kc, tid);
        __syncthreads();
        mma_chunk(c, ACTH + kc * 64, ACTL + kc * 64, BMH, BML, warpM, warpN, lane);
    }
    __syncthreads();
    epi_bf(c, ACTH, ACTL, wk_b, s_s, s_ss, warpM, warpN, g, tig);  // act = x_k
    __syncthreads();
    float esck = expf(*wk_s);
    if (tid < 128) {
        float x0 = rc(ACTH, ACTL, tid * LDA);
        float t  = esck / (1.f + expf(-x0)) + 1.1f;
        s_t[tid]  = t;
        s_s[tid]  = sqrtf((t * t - 1.f) / fmaxf(s_ss[tid], 1e-8f));
        s_ss[tid] = 0.f;
    }
    __syncthreads();

    // logits + ssum atomics
    float attv = *att;
    for (int i = 0; i < 16; i++) {
        int r = wid * 16 + i;
        int dv = s_dst[r];
        float inner = 0.f;
        float sk = s_s[r];
        if (dv >= 0) {
            #pragma unroll
            for (int cc = 0; cc < 4; cc++) {
                int col = lane + cc * 32;
                if (col > 0)
                    inner = fmaf(sk * rc(ACTH, ACTL, r * LDA + col),
                                 g_QhD[(size_t)dv * 128 + col], inner);
            }
        }
        inner = warp_reduce_sum(inner);
        if (lane == 0 && dv >= 0) {
            inner -= s_t[r] * g_QhD[(size_t)dv * 128];
            float wgt = expf((2.f + 2.f * inner) / attv);
            s_w[r] = wgt;
            atomicAdd(&g_ssum[dv], wgt);
        }
    }
    __syncthreads();

    // GEMM wv: x_k -> x_v
    zero_c(c);
    for (int kc = 0; kc < 2; kc++) {
        __syncthreads();
        stage_W(BMH, BML, g_Wh_v, g_Wl_v, 128, kc, tid);
        __syncthreads();
        mma_chunk(c, ACTH + kc * 64, ACTL + kc * 64, BMH, BML, warpM, warpN, lane);
    }
    __syncthreads();
    epi_bf(c, ACTH, ACTL, wv_b, s_s, s_ss, warpM, warpN, g, tig);  // act = x_v
    __syncthreads();
    float escv = expf(*wv_s);
    if (tid < 128) {
        float x0 = rc(ACTH, ACTL, tid * LDA);
        float t  = escv / (1.f + expf(-x0)) + 1.1f;
        s_t[tid] = t;
        s_s[tid] = sqrtf((t * t - 1.f) / fmaxf(s_ss[tid], 1e-8f));
    }
    __syncthreads();

    // weighted scatter
    for (int i = 0; i < 16; i++) {
        int r = wid * 16 + i;
        int dv = s_dst[r];
        if (dv < 0) continue;
        float wgt = s_w[r], s3 = s_s[r], t3 = s_t[r];
        #pragma unroll
        for (int cc = 0; cc < 4; cc++) {
            int col = lane + cc * 32;
            float v = (col == 0) ? t3 : rc(ACTH, ACTL, r * LDA + col) * s3;
            atomicAdd(&g_acc[(size_t)dv * 128 + col], wgt * v);
        }
    }
}

// ---------------- finalize ----------------
__global__ void finalize_kernel(float* __restrict__ out) {
    int d = blockIdx.x * 4 + (threadIdx.x >> 5);
    int lane = threadIdx.x & 31;
    if (d >= cD) return;
    float inv_s = 1.f / g_ssum[d];
    float rv[4];
    float sq = 0.f;
    #pragma unroll
    for (int i = 0; i < 4; i++) {
        int c = lane + 32 * i;
        float v = g_acc[(size_t)d * 128 + c] * inv_s;
        rv[i] = v;
        if (c != 0) sq += v * v;
    }
    sq = warp_reduce_sum(sq);
    float r0 = __shfl_sync(0xffffffffu, rv[0], 0);
    float neg_inner = r0 * r0 - sq;
    float denom = sqrtf(fmaxf(fabsf(neg_inner), 1e-8f));
    float a = fmaxf(r0 / denom, 1.f + 1e-7f);
    float coef = acoshf(a) / sqrtf(fmaxf(a * a - 1.f, 1e-8f));
    #pragma unroll
    for (int i = 0; i < 4; i++) {
        int c = lane + 32 * i;
        out[(size_t)d * 128 + c] = (c == 0) ? 0.f : coef * (rv[i] / denom);
    }
}

// ---------------- launch ----------------
extern "C" void kernel_launch(void* const* d_in, const int* in_sizes, int n_in,
                              void* d_out, int out_size) {
    const float* h     = (const float*)d_in[0];
    const float* ef    = (const float*)d_in[1];
    const float* dt    = (const float*)d_in[2];
    const float* te_w  = (const float*)d_in[3];
    const float* te_b  = (const float*)d_in[4];
    const float* lq_W  = (const float*)d_in[5];
    const float* lq_b  = (const float*)d_in[6];
    const float* lq_s  = (const float*)d_in[7];
    const float* lkv_W = (const float*)d_in[8];
    const float* lkv_b = (const float*)d_in[9];
    const float* lkv_s = (const float*)d_in[10];
    const float* wq_W  = (const float*)d_in[11];
    const float* wq_b  = (const float*)d_in[12];
    const float* wq_s  = (const float*)d_in[13];
    const float* wk_W  = (const float*)d_in[14];
    const float* wk_b  = (const float*)d_in[15];
    const float* wk_s  = (const float*)d_in[16];
    const float* wv_W  = (const float*)d_in[17];
    const float* wv_b  = (const float*)d_in[18];
    const float* wv_s  = (const float*)d_in[19];
    const float* att   = (const float*)d_in[20];
    const int*   edst  = (const int*)d_in[21];
    float* out = (float*)d_out;

    cudaFuncSetAttribute(d_kernel, cudaFuncAttributeMaxDynamicSharedMemorySize, D_TOTAL_B);
    cudaFuncSetAttribute(e_kernel, cudaFuncAttributeMaxDynamicSharedMemorySize, E_TOTAL_B);

    prep_weights<<<dim3((128 * KVFP + 255) / 256, 5), 256>>>(lq_W, lkv_W, wq_W, wk_W, wv_W);
    d_kernel<<<(cD + 127) / 128, 256, D_TOTAL_B>>>(
        h, te_b, lq_b, lq_s, wq_b, wq_s, wk_b, wk_s, wv_b, wv_s, att);
    e_kernel<<<(cE + 127) / 128, 256, E_TOTAL_B>>>(
        h, ef, dt, te_w, te_b, lkv_b, lkv_s, wk_b, wk_s, wv_b, wv_s, att, edst);
    finalize_kernel<<<(cD + 3) / 4, 128>>>(out);
}